// round 8
// baseline (speedup 1.0000x reference)
#include <cuda_runtime.h>

// Problem constants (fixed by the dataset)
#define BATCH   8
#define LEN     4096
#define NK      128          // number of 2x2 rotor blocks
#define NSTATE  256          // state size = NK*2
#define M_TOTAL (BATCH*LEN)  // 32768 rows for both GEMMs
#define NCH     64           // scan chunks per sequence
#define LC      64           // chunk length (LEN/NCH), power of two
#define LOG2LC  6
#define OUT_Y   ((size_t)BATCH*LEN*NSTATE)  // y elements before new_state tail

// Scratch (device globals: no allocation allowed in kernel_launch)
__device__ float  g_uB[(size_t)M_TOTAL * NSTATE];   // u @ B
__device__ float  g_x [(size_t)M_TOTAL * NSTATE];   // scanned states
__device__ float2 g_h   [BATCH * NCH * NK];         // per-chunk local partials
__device__ float2 g_init[BATCH * NCH * NK];         // per-chunk entry states

// ---------------------------------------------------------------------------
// fp32 SIMT GEMM: C[M,N] = A[M,K] * B[K,N], 128x128 tile, 8x8 per thread
// ---------------------------------------------------------------------------
#define BM  128
#define BN  128
#define BKT 16
#define TM  8
#define TN  8

__global__ __launch_bounds__(256) void gemm_f32(
    const float* __restrict__ Am, const float* __restrict__ Bm,
    float* __restrict__ Cm, int M, int N, int Kd)
{
    __shared__ float As[BKT][BM];   // A stored transposed: As[k][m]
    __shared__ float Bs[BKT][BN];

    const int tid = threadIdx.x;
    const int tx  = tid & 15;     // column group (0..15)
    const int ty  = tid >> 4;     // row group    (0..15)
    const int blockRow = blockIdx.y * BM;
    const int blockCol = blockIdx.x * BN;

    float acc[TM][TN];
#pragma unroll
    for (int i = 0; i < TM; i++)
#pragma unroll
        for (int j = 0; j < TN; j++) acc[i][j] = 0.f;

    float ar[TM], br[TN];

    for (int k0 = 0; k0 < Kd; k0 += BKT) {
        // Load A tile: 128x16 floats = 512 float4; each thread loads 2
#pragma unroll
        for (int i = 0; i < 2; i++) {
            int f  = tid + i * 256;
            int r  = f >> 2;            // row within tile (0..127)
            int c4 = (f & 3) * 4;       // k offset (0,4,8,12)
            float4 v = *(const float4*)(Am + (size_t)(blockRow + r) * Kd + k0 + c4);
            As[c4 + 0][r] = v.x;
            As[c4 + 1][r] = v.y;
            As[c4 + 2][r] = v.z;
            As[c4 + 3][r] = v.w;
        }
        // Load B tile: 16x128 floats = 512 float4; each thread loads 2
#pragma unroll
        for (int i = 0; i < 2; i++) {
            int f  = tid + i * 256;
            int r  = f >> 5;            // k row (0..15)
            int c4 = (f & 31) * 4;      // col offset (0..124)
            *(float4*)(&Bs[r][c4]) =
                *(const float4*)(Bm + (size_t)(k0 + r) * N + blockCol + c4);
        }
        __syncthreads();

#pragma unroll
        for (int kk = 0; kk < BKT; kk++) {
            *(float4*)(&ar[0]) = *(const float4*)(&As[kk][ty * TM + 0]);
            *(float4*)(&ar[4]) = *(const float4*)(&As[kk][ty * TM + 4]);
            *(float4*)(&br[0]) = *(const float4*)(&Bs[kk][tx * TN + 0]);
            *(float4*)(&br[4]) = *(const float4*)(&Bs[kk][tx * TN + 4]);
#pragma unroll
            for (int i = 0; i < TM; i++)
#pragma unroll
                for (int j = 0; j < TN; j++)
                    acc[i][j] = fmaf(ar[i], br[j], acc[i][j]);
        }
        __syncthreads();
    }

#pragma unroll
    for (int i = 0; i < TM; i++) {
        float* crow = Cm + (size_t)(blockRow + ty * TM + i) * N + blockCol + tx * TN;
        *(float4*)(crow + 0) = make_float4(acc[i][0], acc[i][1], acc[i][2], acc[i][3]);
        *(float4*)(crow + 4) = make_float4(acc[i][4], acc[i][5], acc[i][6], acc[i][7]);
    }
}

// ---------------------------------------------------------------------------
// Scan phase 1: per-chunk local scan with zero initial state
// grid: (NCH, BATCH) x 128 threads (one rotor per thread)
// ---------------------------------------------------------------------------
__global__ __launch_bounds__(NK) void scan_partial(const float* __restrict__ A)
{
    const int k  = threadIdx.x;
    const int ch = blockIdx.x;
    const int b  = blockIdx.y;
    const float c = A[4 * k + 0];
    const float s = A[4 * k + 1];

    const float2* base = reinterpret_cast<const float2*>(g_uB)
                       + (size_t)(b * LEN + ch * LC) * NK + k;
    float zx = 0.f, zy = 0.f;
#pragma unroll 8
    for (int l = 0; l < LC; l++) {
        float2 w = base[(size_t)l * NK];
        float nx = fmaf(zx, c, fmaf(-zy, s, w.x));
        float ny = fmaf(zx, s, fmaf( zy, c, w.y));
        zx = nx; zy = ny;
    }
    g_h[((size_t)b * NCH + ch) * NK + k] = make_float2(zx, zy);
}

// ---------------------------------------------------------------------------
// Scan phase 2: sequential prefix across chunks (R^LC by double-prec squaring)
// grid: BATCH x 128 threads
// ---------------------------------------------------------------------------
__global__ __launch_bounds__(NK) void scan_prefix(
    const float* __restrict__ A, const float* __restrict__ x0)
{
    const int k = threadIdx.x;
    const int b = blockIdx.x;

    double cd = (double)A[4 * k + 0];
    double sd = (double)A[4 * k + 1];
#pragma unroll
    for (int i = 0; i < LOG2LC; i++) {      // (c,s) <- rotation angle doubling
        double nc = cd * cd - sd * sd;
        double ns = 2.0 * cd * sd;
        cd = nc; sd = ns;
    }
    const float Cc = (float)cd, Ss = (float)sd;

    float zx = x0[((size_t)b * NK + k) * 2 + 0];
    float zy = x0[((size_t)b * NK + k) * 2 + 1];
    for (int ch = 0; ch < NCH; ch++) {
        size_t idx = ((size_t)b * NCH + ch) * NK + k;
        g_init[idx] = make_float2(zx, zy);
        float2 h = g_h[idx];
        float nx = fmaf(zx, Cc, fmaf(-zy, Ss, h.x));
        float ny = fmaf(zx, Ss, fmaf( zy, Cc, h.y));
        zx = nx; zy = ny;
    }
}

// ---------------------------------------------------------------------------
// Scan phase 3: replay with correct entry states, write x and new_state
// grid: (NCH, BATCH) x 128 threads
// ---------------------------------------------------------------------------
__global__ __launch_bounds__(NK) void scan_replay(
    const float* __restrict__ A, float* __restrict__ out)
{
    const int k  = threadIdx.x;
    const int ch = blockIdx.x;
    const int b  = blockIdx.y;
    const float c = A[4 * k + 0];
    const float s = A[4 * k + 1];

    const size_t idx = ((size_t)b * NCH + ch) * NK + k;
    float2 z0 = g_init[idx];
    float zx = z0.x, zy = z0.y;

    const float2* src = reinterpret_cast<const float2*>(g_uB)
                      + (size_t)(b * LEN + ch * LC) * NK + k;
    float2* dst = reinterpret_cast<float2*>(g_x)
                + (size_t)(b * LEN + ch * LC) * NK + k;

#pragma unroll 8
    for (int l = 0; l < LC; l++) {
        float2 w = src[(size_t)l * NK];
        float nx = fmaf(zx, c, fmaf(-zy, s, w.x));
        float ny = fmaf(zx, s, fmaf( zy, c, w.y));
        zx = nx; zy = ny;
        dst[(size_t)l * NK] = make_float2(zx, zy);
    }
    if (ch == NCH - 1) {   // new_state = x[:, -1]
        out[OUT_Y + ((size_t)b * NK + k) * 2 + 0] = zx;
        out[OUT_Y + ((size_t)b * NK + k) * 2 + 1] = zy;
    }
}

// ---------------------------------------------------------------------------
// Launch: u@B -> scan (3 phases) -> x@C (+ new_state tail written in replay)
// ---------------------------------------------------------------------------
extern "C" void kernel_launch(void* const* d_in, const int* in_sizes, int n_in,
                              void* d_out, int out_size)
{
    const float* u  = (const float*)d_in[0];
    const float* x0 = (const float*)d_in[1];
    const float* A  = (const float*)d_in[2];
    const float* B  = (const float*)d_in[3];
    const float* C  = (const float*)d_in[4];
    float* out = (float*)d_out;
    (void)in_sizes; (void)n_in; (void)out_size;

    float *uBp = nullptr, *xp = nullptr;
    cudaGetSymbolAddress((void**)&uBp, g_uB);
    cudaGetSymbolAddress((void**)&xp,  g_x);

    dim3 gemm_grid(NSTATE / BN, M_TOTAL / BM);   // (2, 256)
    gemm_f32<<<gemm_grid, 256>>>(u, B, uBp, M_TOTAL, NSTATE, NSTATE);

    scan_partial<<<dim3(NCH, BATCH), NK>>>(A);
    scan_prefix<<<BATCH, NK>>>(A, x0);
    scan_replay<<<dim3(NCH, BATCH), NK>>>(A, out);

    gemm_f32<<<gemm_grid, 256>>>(xp, C, out, M_TOTAL, NSTATE, NSTATE);
}